// round 1
// baseline (speedup 1.0000x reference)
#include <cuda_runtime.h>

namespace {
constexpr int B_  = 4;
constexpr int C_  = 64;
constexpr int IC_ = 16;
constexpr int D_  = 8;
constexpr int H_  = 128;
constexpr int W_  = 128;
constexpr int MID_ = 4;
constexpr int HP_ = 64;   // (128+2-3)/2+1
constexpr int L_  = 4096; // HP*WP
constexpr int F_  = 144;  // IC*3*3
constexpr float SCALE_ = 10.0f;

// shared-memory layout (floats) for flash kernel
constexpr int QST_STRIDE = 132;  // 128 rows + pad (16B aligned stride)
constexpr int KST_STRIDE = 68;   // 64 cols + pad
constexpr int VS_STRIDE  = 148;  // 144 f + pad
constexpr int PST_STRIDE = 132;
constexpr int QST_OFF = 0;                         // [144][132]
constexpr int KST_OFF = QST_OFF + 144 * QST_STRIDE; // 19008, [144][68]
constexpr int VS_OFF  = KST_OFF + 144 * KST_STRIDE; // 28800, [64][148]
constexpr int PST_OFF = VS_OFF  + 64  * VS_STRIDE;  // 38272, [64][132]
constexpr int SMEM_FLOATS = PST_OFF + 64 * PST_STRIDE; // 46720
constexpr int SMEM_BYTES  = SMEM_FLOATS * 4;           // 186880
}

// ---- scratch (device globals; no runtime allocation allowed) ----
__device__ float d_conv[3][B_][IC_][H_][W_];   // 0:q-map(g_w on s), 1:v-map(theta on g), 2:k-map(phi on g)
__device__ float d_qkv[3][B_][L_][F_];         // 0:q 1:v 2:k
__device__ float d_zi[B_][L_][F_];             // attention output rows
__device__ float d_yvec[B_][C_][H_][W_];       // W_w @ z + bias (broadcast over D)

// ============================================================
// Kernel 1: 1x1 convs at the mid depth slice only.
// grid (H, B), 128 threads (one per x)
// ============================================================
__global__ void k_conv(const float* __restrict__ s, const float* __restrict__ g,
                       const float* __restrict__ gw, const float* __restrict__ gb,
                       const float* __restrict__ tw, const float* __restrict__ tb,
                       const float* __restrict__ pw, const float* __restrict__ pb) {
    __shared__ float wq[IC_ * C_], wv[IC_ * C_], wk[IC_ * C_];
    __shared__ float bq[IC_], bv[IC_], bk[IC_];
    const int tid = threadIdx.x;
    for (int i = tid; i < IC_ * C_; i += 128) { wq[i] = gw[i]; wv[i] = tw[i]; wk[i] = pw[i]; }
    if (tid < IC_) { bq[tid] = gb[tid]; bv[tid] = tb[tid]; bk[tid] = pb[tid]; }
    __syncthreads();

    const int y = blockIdx.x, b = blockIdx.y, x = tid;
    float aq[IC_], av[IC_], ak[IC_];
#pragma unroll
    for (int ic = 0; ic < IC_; ic++) { aq[ic] = bq[ic]; av[ic] = bv[ic]; ak[ic] = bk[ic]; }

    // s[b,0,c,MID,y,x] : base + c * (D*H*W)
    const size_t base = ((size_t)b * C_ * D_ + MID_) * (H_ * W_) + (size_t)y * W_ + x;
    const size_t cstride = (size_t)D_ * H_ * W_;
#pragma unroll 4
    for (int c = 0; c < C_; c++) {
        const float sv = s[base + c * cstride];
        const float gv = g[base + c * cstride];
#pragma unroll
        for (int ic = 0; ic < IC_; ic++) {
            aq[ic] += wq[ic * C_ + c] * sv;
            av[ic] += wv[ic * C_ + c] * gv;
            ak[ic] += wk[ic * C_ + c] * gv;
        }
    }
#pragma unroll
    for (int ic = 0; ic < IC_; ic++) {
        const int o = ((b * IC_ + ic) * H_ + y) * W_ + x;
        (&d_conv[0][0][0][0][0])[o] = aq[ic];
        (&d_conv[1][0][0][0][0])[o] = av[ic];
        (&d_conv[2][0][0][0][0])[o] = ak[ic];
    }
}

// ============================================================
// Kernel 2: patch extraction -> q/v/k matrices [b][l][144]
// one thread per (b,l,f); total B*L*F = 2,359,296
// ============================================================
__global__ void k_patch() {
    const int idx = blockIdx.x * 256 + threadIdx.x;
    if (idx >= B_ * L_ * F_) return;
    const int f = idx % F_;
    const int t = idx / F_;
    const int l = t & (L_ - 1);
    const int b = t >> 12;
    const int c  = f / 9;
    const int r  = f - c * 9;
    const int ki = r / 3;
    const int kj = r - ki * 3;
    const int hp = l >> 6, wp = l & 63;
    const int y = hp * 2 - 1 + ki;
    const int x = wp * 2 - 1 + kj;
    const bool in = ((unsigned)y < (unsigned)H_) && ((unsigned)x < (unsigned)W_);
#pragma unroll
    for (int m = 0; m < 3; m++) {
        float val = in ? d_conv[m][b][c][y][x] : 0.0f;
        d_qkv[m][b][l][f] = val;
    }
}

// ============================================================
// Kernel 3: flash attention, fp32.
// grid (L/128, B), 512 threads = 32(ty) x 16(tx).
// Row tile BR=128, col tile BC=64. Per thread: 4x4 S micro-tile,
// O accumulator 4 rows x 9 f-cols.
// ============================================================
__global__ __launch_bounds__(512, 1) void k_flash() {
    extern __shared__ float sm[];
    float* Qst = sm + QST_OFF;   // [f][row]
    float* Kst = sm + KST_OFF;   // [f][col]
    float* Vs  = sm + VS_OFF;    // [col][f]
    float* Pst = sm + PST_OFF;   // [col][row]

    const int tid = threadIdx.x;
    const int tx = tid & 15;     // 0..15
    const int ty = tid >> 4;     // 0..31
    const int b = blockIdx.y;
    const int row0 = blockIdx.x * 128;

    const float* __restrict__ qg = &d_qkv[0][b][0][0];
    const float* __restrict__ vg = &d_qkv[1][b][0][0];
    const float* __restrict__ kg = &d_qkv[2][b][0][0];

    // fill Q tile (transposed into smem)
    for (int e = tid; e < 128 * F_; e += 512) {
        const int r = e / F_, f = e - r * F_;
        Qst[f * QST_STRIDE + r] = qg[(row0 + r) * F_ + f];
    }

    float m_i[4], l_i[4], O[4][9];
#pragma unroll
    for (int i = 0; i < 4; i++) {
        m_i[i] = -1e30f; l_i[i] = 0.f;
#pragma unroll
        for (int u = 0; u < 9; u++) O[i][u] = 0.f;
    }

    const float* qp = Qst + ty * 4;
    const float* kp = Kst + tx * 4;
    const float* pp = Pst + ty * 4;
    const float* vp = Vs + tx * 9;

    for (int ct = 0; ct < 64; ct++) {
        const int col0 = ct * 64;
        for (int e = tid; e < 64 * F_; e += 512) {
            const int c = e / F_, f = e - c * F_;
            Kst[f * KST_STRIDE + c] = kg[(col0 + c) * F_ + f];
            Vs[c * VS_STRIDE + f]   = vg[(col0 + c) * F_ + f];
        }
        __syncthreads();

        // ---- S = Q K^T (tile 128x64) ----
        float acc[4][4];
#pragma unroll
        for (int i = 0; i < 4; i++)
#pragma unroll
            for (int j = 0; j < 4; j++) acc[i][j] = 0.f;

#pragma unroll 4
        for (int f = 0; f < F_; f++) {
            const float4 qv = *reinterpret_cast<const float4*>(qp + f * QST_STRIDE);
            const float4 kv = *reinterpret_cast<const float4*>(kp + f * KST_STRIDE);
            acc[0][0] += qv.x * kv.x; acc[0][1] += qv.x * kv.y; acc[0][2] += qv.x * kv.z; acc[0][3] += qv.x * kv.w;
            acc[1][0] += qv.y * kv.x; acc[1][1] += qv.y * kv.y; acc[1][2] += qv.y * kv.z; acc[1][3] += qv.y * kv.w;
            acc[2][0] += qv.z * kv.x; acc[2][1] += qv.z * kv.y; acc[2][2] += qv.z * kv.z; acc[2][3] += qv.z * kv.w;
            acc[3][0] += qv.w * kv.x; acc[3][1] += qv.w * kv.y; acc[3][2] += qv.w * kv.z; acc[3][3] += qv.w * kv.w;
        }

        // ---- online softmax ----
#pragma unroll
        for (int i = 0; i < 4; i++)
#pragma unroll
            for (int j = 0; j < 4; j++) acc[i][j] *= SCALE_;

        float mloc[4], rs[4], alpha[4];
#pragma unroll
        for (int i = 0; i < 4; i++)
            mloc[i] = fmaxf(fmaxf(acc[i][0], acc[i][1]), fmaxf(acc[i][2], acc[i][3]));
#pragma unroll
        for (int off = 8; off >= 1; off >>= 1)
#pragma unroll
            for (int i = 0; i < 4; i++)
                mloc[i] = fmaxf(mloc[i], __shfl_xor_sync(0xffffffffu, mloc[i], off, 16));

#pragma unroll
        for (int i = 0; i < 4; i++) {
            const float mn = fmaxf(m_i[i], mloc[i]);
            alpha[i] = __expf(m_i[i] - mn);
            m_i[i] = mn;
            float r = 0.f;
#pragma unroll
            for (int j = 0; j < 4; j++) { acc[i][j] = __expf(acc[i][j] - mn); r += acc[i][j]; }
            rs[i] = r;
        }
#pragma unroll
        for (int off = 8; off >= 1; off >>= 1)
#pragma unroll
            for (int i = 0; i < 4; i++)
                rs[i] += __shfl_xor_sync(0xffffffffu, rs[i], off, 16);
#pragma unroll
        for (int i = 0; i < 4; i++) l_i[i] = l_i[i] * alpha[i] + rs[i];

        // store P transposed, rescale O
#pragma unroll
        for (int j = 0; j < 4; j++)
#pragma unroll
            for (int i = 0; i < 4; i++)
                Pst[(tx * 4 + j) * PST_STRIDE + ty * 4 + i] = acc[i][j];
#pragma unroll
        for (int i = 0; i < 4; i++)
#pragma unroll
            for (int u = 0; u < 9; u++) O[i][u] *= alpha[i];
        __syncthreads();

        // ---- O += P V ----
#pragma unroll 2
        for (int c = 0; c < 64; c++) {
            const float4 pv = *reinterpret_cast<const float4*>(pp + c * PST_STRIDE);
            const float* vr = vp + c * VS_STRIDE;
#pragma unroll
            for (int u = 0; u < 9; u++) {
                const float vvv = vr[u];
                O[0][u] += pv.x * vvv;
                O[1][u] += pv.y * vvv;
                O[2][u] += pv.z * vvv;
                O[3][u] += pv.w * vvv;
            }
        }
        __syncthreads();
    }

    // normalize + write zi
#pragma unroll
    for (int i = 0; i < 4; i++) {
        const float inv = 1.0f / l_i[i];
        const int row = row0 + ty * 4 + i;
#pragma unroll
        for (int u = 0; u < 9; u++)
            d_zi[b][row][tx * 9 + u] = O[i][u] * inv;
    }
}

// ============================================================
// Kernel 4: fold (overlap-add + count normalize) + W_w conv -> yvec
// grid (H, B), 128 threads (one per x)
// ============================================================
__global__ void k_fold(const float* __restrict__ Wmat, const float* __restrict__ Wb) {
    __shared__ float zs[IC_][W_];
    __shared__ float wsm[C_ * IC_];
    __shared__ float bsm[C_];
    const int x = threadIdx.x;
    const int y = blockIdx.x, b = blockIdx.y;
    for (int i = x; i < C_ * IC_; i += 128) wsm[i] = Wmat[i];
    if (x < C_) bsm[x] = Wb[x];

    float v[IC_];
#pragma unroll
    for (int ic = 0; ic < IC_; ic++) v[ic] = 0.f;
    int cnt = 0;
#pragma unroll
    for (int i = 0; i < 3; i++) {
        const int tY = y + 1 - i;
        if (tY < 0 || (tY & 1) || (tY >> 1) >= HP_) continue;
        const int hp = tY >> 1;
#pragma unroll
        for (int j = 0; j < 3; j++) {
            const int tX = x + 1 - j;
            if (tX < 0 || (tX & 1) || (tX >> 1) >= HP_) continue;
            const int wp = tX >> 1;
            const float* zrow = &d_zi[b][hp * 64 + wp][0];
            cnt++;
#pragma unroll
            for (int ic = 0; ic < IC_; ic++) v[ic] += zrow[ic * 9 + i * 3 + j];
        }
    }
    const float invc = 1.0f / (float)cnt;
#pragma unroll
    for (int ic = 0; ic < IC_; ic++) zs[ic][x] = v[ic] * invc;
    __syncthreads();

    for (int o = 0; o < C_; o++) {
        float a = bsm[o];
#pragma unroll
        for (int ic = 0; ic < IC_; ic++) a += wsm[o * IC_ + ic] * zs[ic][x];
        d_yvec[b][o][y][x] = a;
    }
}

// ============================================================
// Kernel 5: out = s + yvec (broadcast over D)
// ============================================================
__global__ void k_out(const float* __restrict__ s, float* __restrict__ out) {
    const int idx = blockIdx.x * 256 + threadIdx.x;
    const int pix = idx & (H_ * W_ - 1);
    const int bo = (idx >> 14) >> 3;  // b*64 + o
    out[idx] = s[idx] + (&d_yvec[0][0][0][0])[bo * (H_ * W_) + pix];
}

// ============================================================
extern "C" void kernel_launch(void* const* d_in, const int* /*in_sizes*/, int /*n_in*/,
                              void* d_out, int /*out_size*/) {
    const float* s   = (const float*)d_in[0];
    const float* g   = (const float*)d_in[1];
    const float* g_w = (const float*)d_in[2];
    const float* g_b = (const float*)d_in[3];
    const float* t_w = (const float*)d_in[4];
    const float* t_b = (const float*)d_in[5];
    const float* p_w = (const float*)d_in[6];
    const float* p_b = (const float*)d_in[7];
    const float* W_w = (const float*)d_in[8];
    const float* W_b = (const float*)d_in[9];
    float* out = (float*)d_out;

    k_conv<<<dim3(H_, B_), 128>>>(s, g, g_w, g_b, t_w, t_b, p_w, p_b);
    k_patch<<<(B_ * L_ * F_) / 256, 256>>>();

    cudaFuncSetAttribute(k_flash, cudaFuncAttributeMaxDynamicSharedMemorySize, SMEM_BYTES);
    k_flash<<<dim3(L_ / 128, B_), 512, SMEM_BYTES>>>();

    k_fold<<<dim3(H_, B_), 128>>>(W_w, W_b);

    const int total = B_ * C_ * D_ * H_ * W_;
    k_out<<<total / 256, 256>>>(s, out);
}